// round 2
// baseline (speedup 1.0000x reference)
#include <cuda_runtime.h>
#include <cstdint>

// Problem shape (fixed by reference): B=32, S=128, V=32000
// loss = -sum_{b,s} prob[b,s,target[b,s]] * reward[b]
//
// True data footprint: 4096 scattered fp32 gathers + 4096 int32 targets + 32
// rewards -> single fp32 scalar. Latency/launch bound, not bandwidth bound.
//
// NOTE: reference says jnp.int64 targets, but JAX with x64 disabled downcasts
// randint(dtype=int64) to int32 — the delivered buffer is int32. R0 read it as
// int64 and gathered at ~10^13 -> illegal memory access.

#define B_ 32
#define S_ 128
#define V_ 32000
#define N_ (B_ * S_)   // 4096

__global__ void rl_loss_kernel(const float* __restrict__ prob,
                               const int* __restrict__ target,
                               const float* __restrict__ reward,
                               float* __restrict__ out) {
    int i = blockIdx.x * blockDim.x + threadIdx.x;  // 0..4095, one (b,s) per thread
    float x = 0.0f;
    if (i < N_) {
        int b = i >> 7;                       // S_ = 128
        int t = target[i];                    // int32 target index in [0, V)
        float v = __ldg(&prob[(long long)i * V_ + t]);
        float r = __ldg(&reward[b]);
        x = -v * r;
    }
    // warp tree-reduce
    #pragma unroll
    for (int off = 16; off > 0; off >>= 1)
        x += __shfl_xor_sync(0xFFFFFFFFu, x, off);
    // one atomic per warp (128 total across the grid)
    if ((threadIdx.x & 31) == 0)
        atomicAdd(out, x);
}

extern "C" void kernel_launch(void* const* d_in, const int* in_sizes, int n_in,
                              void* d_out, int out_size) {
    // Identify inputs by element count, robust to ordering:
    //   prob: B*S*V = 131,072,000   target: B*S = 4096   reward: B = 32
    const float* prob   = nullptr;
    const int*   target = nullptr;
    const float* reward = nullptr;
    for (int k = 0; k < n_in; k++) {
        if (in_sizes[k] == N_ * V_)      prob   = (const float*)d_in[k];
        else if (in_sizes[k] == N_)      target = (const int*)d_in[k];
        else if (in_sizes[k] == B_)      reward = (const float*)d_in[k];
    }
    float* out = (float*)d_out;

    // d_out is poisoned to 0xAA by the harness; zero it (graph-capturable async node)
    cudaMemsetAsync(out, 0, sizeof(float));

    // 32 CTAs x 128 threads = 4096 threads, one gather each.
    rl_loss_kernel<<<32, 128>>>(prob, target, reward, out);
}

// round 3
// speedup vs baseline: 1.1981x; 1.1981x over previous
#include <cuda_runtime.h>
#include <cstdint>

// Problem shape (fixed by reference): B=32, S=128, V=32000
// loss = -sum_{b,s} prob[b,s,target[b,s]] * reward[b]
//
// True footprint: 4096 scattered fp32 gathers + 4096 int32 targets + 32
// rewards -> one fp32 scalar. Latency-bound. R2 post-mortem: 128 same-address
// atomicAdds (~2us serialized) + memset graph node (~2us) dominated. This
// version: single kernel node, per-CTA smem reduce, last-block final combine
// (zero atomics on the output, plain store overwrites harness poison).

#define B_ 32
#define S_ 128
#define V_ 32000
#define N_ (B_ * S_)      // 4096
#define NCTA_ 32

__device__ float g_partials[NCTA_];
__device__ unsigned int g_ticket = 0;   // self-resets to 0 every launch

__global__ void rl_loss_kernel(const float* __restrict__ prob,
                               const int* __restrict__ target,
                               const float* __restrict__ reward,
                               float* __restrict__ out) {
    __shared__ float s_warp[4];
    __shared__ bool s_last;

    int i = blockIdx.x * blockDim.x + threadIdx.x;   // 0..4095
    int b = i >> 7;                                  // S_ = 128
    int t = __ldg(&target[i]);                       // int32 index in [0, V)
    float v = __ldg(&prob[(long long)i * V_ + t]);   // scattered DRAM gather
    float r = __ldg(&reward[b]);
    float x = v * r;

    // warp tree-reduce
    #pragma unroll
    for (int off = 16; off > 0; off >>= 1)
        x += __shfl_xor_sync(0xFFFFFFFFu, x, off);

    int warp = threadIdx.x >> 5;
    if ((threadIdx.x & 31) == 0) s_warp[warp] = x;
    __syncthreads();

    if (threadIdx.x == 0) {
        float p = s_warp[0] + s_warp[1] + s_warp[2] + s_warp[3];
        g_partials[blockIdx.x] = p;
        __threadfence();
        unsigned int tk = atomicAdd(&g_ticket, 1u);
        s_last = (tk == NCTA_ - 1);
    }
    __syncthreads();

    // Last CTA to arrive: combine the 32 partials, write final result.
    if (s_last && threadIdx.x < 32) {
        float p = g_partials[threadIdx.x];
        #pragma unroll
        for (int off = 16; off > 0; off >>= 1)
            p += __shfl_xor_sync(0xFFFFFFFFu, p, off);
        if (threadIdx.x == 0) {
            *out = -p;                       // overwrites poison; no memset node
            atomicExch(&g_ticket, 0u);       // reset for next graph replay
        }
    }
}

extern "C" void kernel_launch(void* const* d_in, const int* in_sizes, int n_in,
                              void* d_out, int out_size) {
    // Identify inputs by element count, robust to ordering:
    //   prob: B*S*V = 131,072,000   target: B*S = 4096   reward: B = 32
    const float* prob   = nullptr;
    const int*   target = nullptr;
    const float* reward = nullptr;
    for (int k = 0; k < n_in; k++) {
        if (in_sizes[k] == N_ * V_)      prob   = (const float*)d_in[k];
        else if (in_sizes[k] == N_)      target = (const int*)d_in[k];
        else if (in_sizes[k] == B_)      reward = (const float*)d_in[k];
    }
    float* out = (float*)d_out;

    // Single graph node: 32 CTAs x 128 threads, one gather each.
    rl_loss_kernel<<<NCTA_, 128>>>(prob, target, reward, out);
}